// round 9
// baseline (speedup 1.0000x reference)
#include <cuda_runtime.h>
#include <cuda_bf16.h>
#include <cstdint>

// ---------------- Problem constants ----------------
#define B_    32
#define H_    128
#define SKV_  8192
#define D_    576      // DIM + TAIL (score dim)
#define DIMV_ 512      // value/output dim
#define TOPK_ 2048
#define SCALE_ 0.041666666666666664f   // 1/sqrt(576)

// ---------------- Tiling ----------------
#define HT    32              // heads per CTA
#define KT    32              // keys per tile
#define NTILES (TOPK_ / KT)   // 64
#define NTHREADS 512          // 16 warps

// smem pitches (in 32-bit words)
#define PQW  292              // Q/K bf16 row pitch (584 bf16; 292%32==4 -> conflict-free frags)
#define PRAW 576              // raw fp32 staging row pitch
#define PS   36               // score/P buffer pitch
#define PPW  36               // P pitch == Sb pitch (aliased)

// smem word offsets
#define OFF_QH   0
#define OFF_QL   (OFF_QH + HT * PQW)        // 9344
#define OFF_KH   (OFF_QL + HT * PQW)        // 18688
#define OFF_KL   (OFF_KH + KT * PQW)        // 28032
#define OFF_RAW  (OFF_KL + KT * PQW)        // 37376
#define OFF_SB0  (OFF_RAW + KT * PRAW)      // 55808
#define OFF_SB1  (OFF_SB0 + HT * PS)        // 56960
#define SMEM_WORDS (OFF_SB1 + 31 * PS + 32) // 58108
#define SMEM_BYTES (SMEM_WORDS * 4)         // 232432 (<= 232448 limit)

#define QL_OFF (OFF_QL - OFF_QH)            // 9344
#define KL_OFF (OFF_KL - OFF_KH)            // 9344
#define PL_OFF (OFF_SB1 - OFF_SB0)          // 1152 (P-hi in Sb0 rows, P-lo in Sb1 rows)

// ---------------- PTX helpers ----------------
__device__ __forceinline__ void mma_bf16(float* d, const uint32_t* a, uint32_t b0, uint32_t b1) {
    asm volatile(
        "mma.sync.aligned.m16n8k16.row.col.f32.bf16.bf16.f32 "
        "{%0,%1,%2,%3},{%4,%5,%6,%7},{%8,%9},{%0,%1,%2,%3};"
        : "+f"(d[0]), "+f"(d[1]), "+f"(d[2]), "+f"(d[3])
        : "r"(a[0]), "r"(a[1]), "r"(a[2]), "r"(a[3]), "r"(b0), "r"(b1));
}

__device__ __forceinline__ void ldsm4t(uint32_t* r, uint32_t saddr) {
    asm volatile("ldmatrix.sync.aligned.m8n8.x4.trans.shared.b16 {%0,%1,%2,%3}, [%4];"
                 : "=r"(r[0]), "=r"(r[1]), "=r"(r[2]), "=r"(r[3]) : "r"(saddr));
}

__device__ __forceinline__ void cp16(uint32_t dst, const void* src) {
    asm volatile("cp.async.cg.shared.global [%0], [%1], 16;" :: "r"(dst), "l"(src));
}
__device__ __forceinline__ void cp_commit() { asm volatile("cp.async.commit_group;"); }
__device__ __forceinline__ void cp_wait_all() { asm volatile("cp.async.wait_group 0;"); }

__device__ __forceinline__ uint32_t pkbf(__nv_bfloat16 lo, __nv_bfloat16 hi) {
    __nv_bfloat162 v = __halves2bfloat162(lo, hi);
    return *reinterpret_cast<uint32_t*>(&v);
}

// split pair of fp32 into (hi, lo) bf16x2 words
__device__ __forceinline__ void split2(float x, float y, uint32_t& h, uint32_t& l) {
    __nv_bfloat16 hx = __float2bfloat16(x);
    __nv_bfloat16 hy = __float2bfloat16(y);
    float rx = x - __bfloat162float(hx);
    float ry = y - __bfloat162float(hy);
    h = pkbf(hx, hy);
    l = pkbf(__float2bfloat16(rx), __float2bfloat16(ry));
}

// ---------------- Kernel ----------------
__global__ __launch_bounds__(NTHREADS, 1)
void sparse_mla_w16_kernel(const float* __restrict__ Qg,
                           const float* __restrict__ KVg,
                           const int*   __restrict__ Idx,
                           float*       __restrict__ Out)
{
    extern __shared__ uint32_t sm[];
    uint32_t* Qh  = sm + OFF_QH;
    uint32_t* Kh  = sm + OFF_KH;
    float*    Raw = (float*)(sm + OFF_RAW);
    float*    Sb0 = (float*)(sm + OFF_SB0);
    float*    Sb1 = (float*)(sm + OFF_SB1);
    uint32_t* Ph  = sm + OFF_SB0;            // P-hi aliased into Sb0 rows (words 0..15)
    float*    SbF = (float*)(sm + OFF_SB0);  // alpha/linv live at col 35 of Sb0 rows

    const int b   = blockIdx.y;
    const int hg  = blockIdx.x;
    const int tid = threadIdx.x;
    const int lane = tid & 31;
    const int w    = tid >> 5;               // 0..15
    const int g    = lane >> 2;
    const int t4   = lane & 3;

    // score-phase warp decomposition: 2 (M) x 4 (N) x 2 (D-half)
    const int mw = w & 1;
    const int nw = (w >> 1) & 3;
    const int dw = w >> 3;
    // AV-phase: warp owns dims [32w, 32w+32)
    const int dv = w * 32;

    // gather/split mapping: 16 threads per KV row
    const int row = tid >> 4;                // 0..31
    const int sub = tid & 15;
    const int* idx_b = Idx + b * TOPK_;
    const uint32_t raw_s = (uint32_t)__cvta_generic_to_shared(Raw + row * PRAW);

    // ---- Prologue: kick off async gather of tile 0, then load+split Q ----
    int pre_idx = idx_b[row];
    {
        const float* src = KVg + ((size_t)b * SKV_ + pre_idx) * D_;
        #pragma unroll
        for (int j = 0; j < 9; j++) {
            const int f4i = sub + 16 * j;
            cp16(raw_s + f4i * 16, src + 4 * f4i);
        }
        cp_commit();
    }
    pre_idx = idx_b[KT + row];               // idx for tile 1

    {
        const float4* src = (const float4*)(Qg + ((size_t)b * H_ + hg * HT + row) * D_);
        #pragma unroll
        for (int j = 0; j < 9; j++) {
            const int f4i = sub + 16 * j;
            float4 v = src[f4i];
            uint32_t h01, l01, h23, l23;
            split2(v.x, v.y, h01, l01);
            split2(v.z, v.w, h23, l23);
            const int base = row * PQW + 2 * f4i;
            *(uint2*)&Qh[base]          = make_uint2(h01, h23);
            *(uint2*)&Qh[base + QL_OFF] = make_uint2(l01, l23);
        }
    }

    // AV accumulators: [mtile][4 dim-pairs][frag] -> 32 dims per warp
    float acc[2][4][4];
    #pragma unroll
    for (int m = 0; m < 2; m++)
        #pragma unroll
        for (int j = 0; j < 4; j++)
            #pragma unroll
            for (int c = 0; c < 4; c++) acc[m][j][c] = 0.f;

    // softmax state: one thread per (head, key-pair); 16-thread groups per head
    float mrow = -1e30f, lrow = 0.f;
    const int sm_head = tid >> 4;            // 0..31
    const int sj      = tid & 15;            // key pair index (keys 2sj, 2sj+1)

    const int lm_rowk = lane & 15;
    const int lm_coln8 = 8 * (lane >> 4);

    for (int t = 0; t < NTILES; t++) {
        cp_wait_all();        // this thread's gather(t) into Raw done
        __syncthreads();      // all gathers visible; AV(t-1) done with Kh/Kl

        // ---- Split pass: Raw (fp32) -> Kh/Kl (bf16 hi/lo) ----
        {
            const float4* rp = (const float4*)(Raw + row * PRAW);
            #pragma unroll
            for (int j = 0; j < 9; j++) {
                const int f4i = sub + 16 * j;
                float4 v = rp[f4i];
                uint32_t h01, l01, h23, l23;
                split2(v.x, v.y, h01, l01);
                split2(v.z, v.w, h23, l23);
                const int base = row * PQW + 2 * f4i;
                *(uint2*)&Kh[base]          = make_uint2(h01, h23);
                *(uint2*)&Kh[base + KL_OFF] = make_uint2(l01, l23);
            }
        }
        __syncthreads();      // split visible; Raw free for next gather

        // ---- Issue async gather of tile t+1 (overlaps compute below) ----
        if (t + 1 < NTILES) {
            const float* src = KVg + ((size_t)b * SKV_ + pre_idx) * D_;
            #pragma unroll
            for (int j = 0; j < 9; j++) {
                const int f4i = sub + 16 * j;
                cp16(raw_s + f4i * 16, src + 4 * f4i);
            }
            cp_commit();
            if (t + 2 < NTILES) pre_idx = idx_b[(t + 2) * KT + row];
        }

        // ---- Score GEMM: warp computes 16 heads x 8 keys over its D-half ----
        {
            float sacc[4] = {0.f, 0.f, 0.f, 0.f};
            const int aRow = 16 * mw + g;
            const int bRow = 8 * nw + g;
            #pragma unroll 3
            for (int ks = 0; ks < 18; ks++) {
                const int kb2 = 144 * dw + 8 * ks;
                const uint32_t* qp = Qh + aRow * PQW + kb2 + t4;
                uint32_t ah[4], al[4];
                ah[0] = qp[0];            ah[1] = qp[8 * PQW];
                ah[2] = qp[4];            ah[3] = qp[8 * PQW + 4];
                al[0] = qp[QL_OFF];       al[1] = qp[QL_OFF + 8 * PQW];
                al[2] = qp[QL_OFF + 4];   al[3] = qp[QL_OFF + 8 * PQW + 4];
                const uint32_t* kp = Kh + bRow * PQW + kb2 + t4;
                uint32_t bh0 = kp[0], bh1 = kp[4];
                uint32_t bl0 = kp[KL_OFF], bl1 = kp[KL_OFF + 4];
                mma_bf16(sacc, ah, bh0, bh1);
                mma_bf16(sacc, ah, bl0, bl1);
                mma_bf16(sacc, al, bh0, bh1);
            }
            float* Sb = dw ? Sb1 : Sb0;
            const int row0 = 16 * mw + g;
            const int col = 8 * nw + 2 * t4;
            *(float2*)&Sb[row0 * PS + col]       = make_float2(sacc[0], sacc[1]);
            *(float2*)&Sb[(row0 + 8) * PS + col] = make_float2(sacc[2], sacc[3]);
        }
        __syncthreads();

        // ---- Softmax (online): thread handles (head, keys 2sj & 2sj+1) ----
        {
            float2 sA = *(const float2*)&Sb0[sm_head * PS + 2 * sj];
            float2 sB = *(const float2*)&Sb1[sm_head * PS + 2 * sj];
            float s0 = (sA.x + sB.x) * SCALE_;
            float s1 = (sA.y + sB.y) * SCALE_;
            float tm = fmaxf(s0, s1);
            #pragma unroll
            for (int off = 1; off < 16; off <<= 1)
                tm = fmaxf(tm, __shfl_xor_sync(0xffffffffu, tm, off));
            const float newm = fmaxf(mrow, tm);
            const float p0 = __expf(s0 - newm);
            const float p1 = __expf(s1 - newm);
            float ts = p0 + p1;
            #pragma unroll
            for (int off = 1; off < 16; off <<= 1)
                ts += __shfl_xor_sync(0xffffffffu, ts, off);
            const float afac = __expf(mrow - newm);
            lrow = lrow * afac + ts;
            mrow = newm;
            // warp-lockstep: all reads of this row (by this warp only) happened above
            if (sj == 0) SbF[sm_head * PS + 35] = afac;     // alpha in col 35
            uint32_t h01, l01;
            split2(p0, p1, h01, l01);
            Ph[sm_head * PPW + sj]          = h01;
            Ph[sm_head * PPW + sj + PL_OFF] = l01;
        }
        __syncthreads();

        // ---- AV: rescale accs, then P(32xKT) x V(KT x 32-dims-of-warp) ----
        {
            const float f0 = SbF[g * PS + 35],        f1 = SbF[(g + 8) * PS + 35];
            const float f2 = SbF[(16 + g) * PS + 35], f3 = SbF[(24 + g) * PS + 35];
            #pragma unroll
            for (int j = 0; j < 4; j++) {
                #pragma unroll
                for (int m = 0; m < 2; m++) {
                    const float fa = m ? f2 : f0;
                    const float fb = m ? f3 : f1;
                    acc[m][j][0] *= fa; acc[m][j][1] *= fa;
                    acc[m][j][2] *= fb; acc[m][j][3] *= fb;
                }
            }
            #pragma unroll
            for (int kk = 0; kk < 2; kk++) {
                uint32_t pah[2][4], pal[2][4];
                #pragma unroll
                for (int m = 0; m < 2; m++) {
                    const uint32_t* pp = Ph + (16 * m + g) * PPW + 8 * kk + t4;
                    pah[m][0] = pp[0];            pah[m][1] = pp[8 * PPW];
                    pah[m][2] = pp[4];            pah[m][3] = pp[8 * PPW + 4];
                    pal[m][0] = pp[PL_OFF];       pal[m][1] = pp[PL_OFF + 8 * PPW];
                    pal[m][2] = pp[PL_OFF + 4];   pal[m][3] = pp[PL_OFF + 8 * PPW + 4];
                }
                #pragma unroll
                for (int jp = 0; jp < 2; jp++) {
                    const int rowk = 16 * kk + lm_rowk;
                    const int coln = dv + 16 * jp + lm_coln8;
                    const uint32_t* vp = Kh + rowk * PQW + (coln >> 1);
                    const uint32_t sah = (uint32_t)__cvta_generic_to_shared(vp);
                    uint32_t bh[4], bl[4];
                    ldsm4t(bh, sah);
                    ldsm4t(bl, sah + KL_OFF * 4);
                    #pragma unroll
                    for (int m = 0; m < 2; m++) {
                        mma_bf16(acc[m][2 * jp],     pah[m], bh[0], bh[1]);
                        mma_bf16(acc[m][2 * jp],     pah[m], bl[0], bl[1]);
                        mma_bf16(acc[m][2 * jp],     pal[m], bh[0], bh[1]);
                        mma_bf16(acc[m][2 * jp + 1], pah[m], bh[2], bh[3]);
                        mma_bf16(acc[m][2 * jp + 1], pah[m], bl[2], bl[3]);
                        mma_bf16(acc[m][2 * jp + 1], pal[m], bh[2], bh[3]);
                    }
                }
            }
        }
    }

    // ---- Epilogue (linv reuses alpha slots -> barrier before overwrite) ----
    __syncthreads();
    if (sj == 0) SbF[sm_head * PS + 35] = 1.0f / lrow;
    __syncthreads();
    {
        const float i0 = SbF[g * PS + 35],        i1 = SbF[(g + 8) * PS + 35];
        const float i2 = SbF[(16 + g) * PS + 35], i3 = SbF[(24 + g) * PS + 35];
        #pragma unroll
        for (int m = 0; m < 2; m++) {
            const float fa = m ? i2 : i0;
            const float fb = m ? i3 : i1;
            const int row0 = 16 * m + g;
            #pragma unroll
            for (int j = 0; j < 4; j++) {
                const int dim = dv + 8 * j + 2 * t4;
                float* o0 = Out + ((size_t)b * H_ + hg * HT + row0) * DIMV_ + dim;
                float* o1 = Out + ((size_t)b * H_ + hg * HT + row0 + 8) * DIMV_ + dim;
                *(float2*)o0 = make_float2(acc[m][j][0] * fa, acc[m][j][1] * fa);
                *(float2*)o1 = make_float2(acc[m][j][2] * fb, acc[m][j][3] * fb);
            }
        }
    }
}

extern "C" void kernel_launch(void* const* d_in, const int* in_sizes, int n_in,
                              void* d_out, int out_size)
{
    const float* Q   = (const float*)d_in[0];
    const float* KV  = (const float*)d_in[1];
    const int*   Idx = (const int*)d_in[2];
    float*       Out = (float*)d_out;

    cudaFuncSetAttribute(sparse_mla_w16_kernel,
                         cudaFuncAttributeMaxDynamicSharedMemorySize, SMEM_BYTES);

    dim3 grid(H_ / HT, B_);   // (4, 32) = 128 CTAs -> one wave
    dim3 block(NTHREADS);
    sparse_mla_w16_kernel<<<grid, block, SMEM_BYTES>>>(Q, KV, Idx, Out);
}

// round 10
// speedup vs baseline: 1.1538x; 1.1538x over previous
#include <cuda_runtime.h>
#include <cuda_bf16.h>
#include <cstdint>

// ---------------- Problem constants ----------------
#define B_    32
#define H_    128
#define SKV_  8192
#define D_    576      // DIM + TAIL (score dim)
#define DIMV_ 512      // value/output dim
#define TOPK_ 2048
#define SCALE_ 0.041666666666666664f   // 1/sqrt(576)

// ---------------- Tiling ----------------
#define HT    32              // heads per CTA
#define KT    32              // keys per tile
#define NTILES (TOPK_ / KT)   // 64
#define NTHREADS 512          // 16 warps

// smem pitches (in 32-bit words)
#define PQW  292              // Q/K bf16 row pitch (584 bf16; %32==4 -> conflict-free frags)
#define PS   36               // score/P buffer pitch (%32==4)
#define PPW  36               // P pitch == Sb pitch (aliased)

// smem word offsets
#define OFF_QH   0
#define OFF_QL   (OFF_QH + HT * PQW)        // 9344
#define OFF_KH   (OFF_QL + HT * PQW)        // 18688
#define OFF_KL   (OFF_KH + KT * PQW)        // 28032
#define OFF_SB0  (OFF_KL + KT * PQW)        // 37376
#define OFF_SB1  (OFF_SB0 + HT * PS)        // 38528
#define OFF_SB2  (OFF_SB1 + HT * PS)        // 39680
#define OFF_SB3  (OFF_SB2 + HT * PS)        // 40832
#define SMEM_WORDS (OFF_SB3 + HT * PS)      // 41984
#define SMEM_BYTES (SMEM_WORDS * 4)         // 167936

#define QL_OFF (OFF_QL - OFF_QH)            // 9344
#define KL_OFF (OFF_KL - OFF_KH)            // 9344
#define PL_OFF (OFF_SB1 - OFF_SB0)          // 1152 (P-hi in Sb0 rows, P-lo in Sb1 rows)

// ---------------- PTX helpers ----------------
__device__ __forceinline__ void mma_bf16(float* d, const uint32_t* a, uint32_t b0, uint32_t b1) {
    asm volatile(
        "mma.sync.aligned.m16n8k16.row.col.f32.bf16.bf16.f32 "
        "{%0,%1,%2,%3},{%4,%5,%6,%7},{%8,%9},{%0,%1,%2,%3};"
        : "+f"(d[0]), "+f"(d[1]), "+f"(d[2]), "+f"(d[3])
        : "r"(a[0]), "r"(a[1]), "r"(a[2]), "r"(a[3]), "r"(b0), "r"(b1));
}

__device__ __forceinline__ void ldsm4(uint32_t* r, uint32_t saddr) {   // non-trans x4
    asm volatile("ldmatrix.sync.aligned.m8n8.x4.shared.b16 {%0,%1,%2,%3}, [%4];"
                 : "=r"(r[0]), "=r"(r[1]), "=r"(r[2]), "=r"(r[3]) : "r"(saddr));
}
__device__ __forceinline__ void ldsm4t(uint32_t* r, uint32_t saddr) {  // trans x4
    asm volatile("ldmatrix.sync.aligned.m8n8.x4.trans.shared.b16 {%0,%1,%2,%3}, [%4];"
                 : "=r"(r[0]), "=r"(r[1]), "=r"(r[2]), "=r"(r[3]) : "r"(saddr));
}

__device__ __forceinline__ uint32_t pkbf(__nv_bfloat16 lo, __nv_bfloat16 hi) {
    __nv_bfloat162 v = __halves2bfloat162(lo, hi);
    return *reinterpret_cast<uint32_t*>(&v);
}

// split pair of fp32 into (hi, lo) bf16x2 words
__device__ __forceinline__ void split2(float x, float y, uint32_t& h, uint32_t& l) {
    __nv_bfloat16 hx = __float2bfloat16(x);
    __nv_bfloat16 hy = __float2bfloat16(y);
    float rx = x - __bfloat162float(hx);
    float ry = y - __bfloat162float(hy);
    h = pkbf(hx, hy);
    l = pkbf(__float2bfloat16(rx), __float2bfloat16(ry));
}

// ---------------- Kernel ----------------
__global__ __launch_bounds__(NTHREADS, 1)
void sparse_mla_xb_kernel(const float* __restrict__ Qg,
                          const float* __restrict__ KVg,
                          const int*   __restrict__ Idx,
                          float*       __restrict__ Out)
{
    extern __shared__ uint32_t sm[];
    uint32_t* Qh  = sm + OFF_QH;
    uint32_t* Kh  = sm + OFF_KH;
    float*    Sb0 = (float*)(sm + OFF_SB0);
    float*    Sb1 = (float*)(sm + OFF_SB1);
    float*    Sb2 = (float*)(sm + OFF_SB2);
    float*    Sb3 = (float*)(sm + OFF_SB3);
    uint32_t* Ph  = sm + OFF_SB0;            // P-hi aliased into Sb0 rows (words 0..15)
    float*    SbF = (float*)(sm + OFF_SB0);  // alpha/linv at col 35 of Sb0 rows

    const int b   = blockIdx.y;
    const int hg  = blockIdx.x;
    const int tid = threadIdx.x;
    const int lane = tid & 31;
    const int w    = tid >> 5;               // 0..15
    const int g    = lane >> 2;
    const int t4   = lane & 3;

    // score-phase decomposition: 2 (M) x 2 (N) x 4 (D-quarter)
    const int mw = w & 1;
    const int nw = (w >> 1) & 1;
    const int dw = w >> 2;                   // 0..3
    // AV-phase: warp owns dims [32w, 32w+32)
    const int dv = w * 32;

    // gather mapping: 16 threads per KV row
    const int row = tid >> 4;                // 0..31
    const int sub = tid & 15;
    const int* idx_b = Idx + b * TOPK_;

    // ldmatrix lane geometry
    const int lm_r8  = (lane & 7) + 8 * ((lane >> 3) & 1);   // row within 16
    const int lm_k4  = 4 * (lane >> 4);                      // +4 words for k+8
    const int lm_rowk = lane & 15;                           // AV V trans rows
    const int lm_coln8 = 8 * (lane >> 4);

    // ---- Prologue: load+split Q; gather+split tile 0 directly ----
    {
        const float4* src = (const float4*)(Qg + ((size_t)b * H_ + hg * HT + row) * D_);
        #pragma unroll
        for (int j = 0; j < 9; j++) {
            const int f4i = sub + 16 * j;
            float4 v = src[f4i];
            uint32_t h01, l01, h23, l23;
            split2(v.x, v.y, h01, l01);
            split2(v.z, v.w, h23, l23);
            const int base = row * PQW + 2 * f4i;
            *(uint2*)&Qh[base]          = make_uint2(h01, h23);
            *(uint2*)&Qh[base + QL_OFF] = make_uint2(l01, l23);
        }
    }
    {
        const int kidx = idx_b[row];
        const float4* src = (const float4*)(KVg + ((size_t)b * SKV_ + kidx) * D_);
        #pragma unroll
        for (int j = 0; j < 9; j++) {
            const int f4i = sub + 16 * j;
            float4 v = src[f4i];
            uint32_t h01, l01, h23, l23;
            split2(v.x, v.y, h01, l01);
            split2(v.z, v.w, h23, l23);
            const int base = row * PQW + 2 * f4i;
            *(uint2*)&Kh[base]          = make_uint2(h01, h23);
            *(uint2*)&Kh[base + KL_OFF] = make_uint2(l01, l23);
        }
    }

    // AV accumulators: [mtile][4 dim-pairs][frag] -> 32 dims per warp
    float acc[2][4][4];
    #pragma unroll
    for (int m = 0; m < 2; m++)
        #pragma unroll
        for (int j = 0; j < 4; j++)
            #pragma unroll
            for (int c = 0; c < 4; c++) acc[m][j][c] = 0.f;

    // softmax state: one thread per (head, key-pair)
    float mrow = -1e30f, lrow = 0.f;
    const int sm_head = tid >> 4;            // 0..31
    const int sj      = tid & 15;

    float4 kvreg[9];                         // in-flight gather of tile t+1

    for (int t = 0; t < NTILES; t++) {
        __syncthreads();    // STS(t) visible; everyone ready

        // ---- Score GEMM: 16 heads x 16 keys over this warp's D-quarter ----
        {
            float sacc[2][4];
            #pragma unroll
            for (int j = 0; j < 2; j++)
                #pragma unroll
                for (int c = 0; c < 4; c++) sacc[j][c] = 0.f;

            const int aRow = 16 * mw;
            #pragma unroll 3
            for (int ks = 0; ks < 9; ks++) {
                const int kb2 = 72 * dw + 8 * ks;
                uint32_t ah[4], al[4];
                {
                    const uint32_t* ap = Qh + (aRow + lm_r8) * PQW + kb2 + lm_k4;
                    const uint32_t sa = (uint32_t)__cvta_generic_to_shared(ap);
                    ldsm4(ah, sa);
                    ldsm4(al, sa + QL_OFF * 4);
                }
                #pragma unroll
                for (int j = 0; j < 2; j++) {
                    const int krow = 16 * nw + 8 * j + g;
                    const uint32_t* kp = Kh + krow * PQW + kb2 + t4;
                    uint32_t bh0 = kp[0], bh1 = kp[4];
                    uint32_t bl0 = kp[KL_OFF], bl1 = kp[KL_OFF + 4];
                    mma_bf16(sacc[j], ah, bh0, bh1);
                    mma_bf16(sacc[j], ah, bl0, bl1);
                    mma_bf16(sacc[j], al, bh0, bh1);
                }
            }
            float* Sb = (dw == 0) ? Sb0 : (dw == 1) ? Sb1 : (dw == 2) ? Sb2 : Sb3;
            const int row0 = 16 * mw + g;
            #pragma unroll
            for (int j = 0; j < 2; j++) {
                const int col = 16 * nw + 8 * j + 2 * t4;
                *(float2*)&Sb[row0 * PS + col]       = make_float2(sacc[j][0], sacc[j][1]);
                *(float2*)&Sb[(row0 + 8) * PS + col] = make_float2(sacc[j][2], sacc[j][3]);
            }
        }
        __syncthreads();

        // ---- Softmax (online) + issue gather LDGs for tile t+1 ----
        if (t + 1 < NTILES) {
            const int kidx = idx_b[(t + 1) * KT + row];
            const float4* src = (const float4*)(KVg + ((size_t)b * SKV_ + kidx) * D_);
            #pragma unroll
            for (int j = 0; j < 9; j++)
                kvreg[j] = src[sub + 16 * j];
        }
        {
            float2 sA = *(const float2*)&Sb0[sm_head * PS + 2 * sj];
            float2 sB = *(const float2*)&Sb1[sm_head * PS + 2 * sj];
            float2 sC = *(const float2*)&Sb2[sm_head * PS + 2 * sj];
            float2 sD = *(const float2*)&Sb3[sm_head * PS + 2 * sj];
            float s0 = (sA.x + sB.x + sC.x + sD.x) * SCALE_;
            float s1 = (sA.y + sB.y + sC.y + sD.y) * SCALE_;
            float tm = fmaxf(s0, s1);
            #pragma unroll
            for (int off = 1; off < 16; off <<= 1)
                tm = fmaxf(tm, __shfl_xor_sync(0xffffffffu, tm, off));
            const float newm = fmaxf(mrow, tm);
            const float p0 = __expf(s0 - newm);
            const float p1 = __expf(s1 - newm);
            float ts = p0 + p1;
            #pragma unroll
            for (int off = 1; off < 16; off <<= 1)
                ts += __shfl_xor_sync(0xffffffffu, ts, off);
            const float afac = __expf(mrow - newm);
            lrow = lrow * afac + ts;
            mrow = newm;
            // warp-lockstep: this warp's reads of these rows happened above
            if (sj == 0) SbF[sm_head * PS + 35] = afac;     // alpha in col 35
            uint32_t h01, l01;
            split2(p0, p1, h01, l01);
            Ph[sm_head * PPW + sj]          = h01;
            Ph[sm_head * PPW + sj + PL_OFF] = l01;
        }
        __syncthreads();

        // ---- AV: rescale accs, then P(32xKT) x V(KT x 32-dims-of-warp) ----
        {
            const float f0 = SbF[g * PS + 35],        f1 = SbF[(g + 8) * PS + 35];
            const float f2 = SbF[(16 + g) * PS + 35], f3 = SbF[(24 + g) * PS + 35];
            #pragma unroll
            for (int j = 0; j < 4; j++) {
                #pragma unroll
                for (int m = 0; m < 2; m++) {
                    const float fa = m ? f2 : f0;
                    const float fb = m ? f3 : f1;
                    acc[m][j][0] *= fa; acc[m][j][1] *= fa;
                    acc[m][j][2] *= fb; acc[m][j][3] *= fb;
                }
            }
            #pragma unroll
            for (int kk = 0; kk < 2; kk++) {
                uint32_t pah[2][4], pal[2][4];
                #pragma unroll
                for (int m = 0; m < 2; m++) {
                    const uint32_t* pp = Ph + (16 * m + lm_r8) * PPW + 8 * kk + lm_k4;
                    const uint32_t sa = (uint32_t)__cvta_generic_to_shared(pp);
                    ldsm4(pah[m], sa);
                    ldsm4(pal[m], sa + PL_OFF * 4);
                }
                #pragma unroll
                for (int jp = 0; jp < 2; jp++) {
                    const int rowk = 16 * kk + lm_rowk;
                    const int coln = dv + 16 * jp + lm_coln8;
                    const uint32_t* vp = Kh + rowk * PQW + (coln >> 1);
                    const uint32_t sah = (uint32_t)__cvta_generic_to_shared(vp);
                    uint32_t bh[4], bl[4];
                    ldsm4t(bh, sah);
                    ldsm4t(bl, sah + KL_OFF * 4);
                    #pragma unroll
                    for (int m = 0; m < 2; m++) {
                        mma_bf16(acc[m][2 * jp],     pah[m], bh[0], bh[1]);
                        mma_bf16(acc[m][2 * jp],     pah[m], bl[0], bl[1]);
                        mma_bf16(acc[m][2 * jp],     pal[m], bh[0], bh[1]);
                        mma_bf16(acc[m][2 * jp + 1], pah[m], bh[2], bh[3]);
                        mma_bf16(acc[m][2 * jp + 1], pah[m], bl[2], bl[3]);
                        mma_bf16(acc[m][2 * jp + 1], pal[m], bh[2], bh[3]);
                    }
                }
            }
        }
        __syncthreads();    // all warps done reading Kh/Kl for tile t

        // ---- Split+store gathered tile t+1 into Kh/Kl ----
        if (t + 1 < NTILES) {
            #pragma unroll
            for (int j = 0; j < 9; j++) {
                const int f4i = sub + 16 * j;
                float4 v = kvreg[j];
                uint32_t h01, l01, h23, l23;
                split2(v.x, v.y, h01, l01);
                split2(v.z, v.w, h23, l23);
                const int base = row * PQW + 2 * f4i;
                *(uint2*)&Kh[base]          = make_uint2(h01, h23);
                *(uint2*)&Kh[base + KL_OFF] = make_uint2(l01, l23);
            }
        }
    }

    // ---- Epilogue (linv reuses alpha slots -> barrier before overwrite) ----
    __syncthreads();
    if (sj == 0) SbF[sm_head * PS + 35] = 1.0f / lrow;
    __syncthreads();
    {
        const float i0 = SbF[g * PS + 35],        i1 = SbF[(g + 8) * PS + 35];
        const float i2 = SbF[(16 + g) * PS + 35], i3 = SbF[(24 + g) * PS + 35];
        #pragma unroll
        for (int m = 0; m < 2; m++) {
            const float fa = m ? i2 : i0;
            const float fb = m ? i3 : i1;
            const int row0 = 16 * m + g;
            #pragma unroll
            for (int j = 0; j < 4; j++) {
                const int dim = dv + 8 * j + 2 * t4;
                float* o0 = Out + ((size_t)b * H_ + hg * HT + row0) * DIMV_ + dim;
                float* o1 = Out + ((size_t)b * H_ + hg * HT + row0 + 8) * DIMV_ + dim;
                *(float2*)o0 = make_float2(acc[m][j][0] * fa, acc[m][j][1] * fa);
                *(float2*)o1 = make_float2(acc[m][j][2] * fb, acc[m][j][3] * fb);
            }
        }
    }
}

extern "C" void kernel_launch(void* const* d_in, const int* in_sizes, int n_in,
                              void* d_out, int out_size)
{
    const float* Q   = (const float*)d_in[0];
    const float* KV  = (const float*)d_in[1];
    const int*   Idx = (const int*)d_in[2];
    float*       Out = (float*)d_out;

    cudaFuncSetAttribute(sparse_mla_xb_kernel,
                         cudaFuncAttributeMaxDynamicSharedMemorySize, SMEM_BYTES);

    dim3 grid(H_ / HT, B_);   // (4, 32) = 128 CTAs -> one wave
    dim3 block(NTHREADS);
    sparse_mla_xb_kernel<<<grid, block, SMEM_BYTES>>>(Q, KV, Idx, Out);
}